// round 9
// baseline (speedup 1.0000x reference)
#include <cuda_runtime.h>
#include <math.h>

#define NNODE 20
#define NEDGE 380
#define HID   64
#define NL    3
#define ETILE 64
#define NTILE 6      // ceil(380/64)
#define SH    68     // stride for h-like [20][*] arrays (float4-aligned)
#define SMM   68     // buf edge-major stride (float4 aligned)
#define BLK   256
#define NB    1024

__device__ __forceinline__ float tanh_a(float v){
    float r; asm("tanh.approx.f32 %0, %1;" : "=f"(r) : "f"(v)); return r;
}
// silu(v) = v*sigmoid(v) = h + h*tanh(h), h = v/2   (1 special op)
__device__ __forceinline__ float silu_f(float v){
    float h = 0.5f * v;
    return fmaf(tanh_a(h), h, h);
}
// sigmoid(v) = 0.5 + 0.5*tanh(v/2)
__device__ __forceinline__ float sigm_f(float v){
    return fmaf(tanh_a(0.5f * v), 0.5f, 0.5f);
}

// packed fp32x2 helpers (sm_103a FFMA2 path — PTX-only, ptxas never auto-fuses)
__device__ __forceinline__ unsigned long long dup2(float v){
    unsigned long long r;
    asm("mov.b64 %0, {%1, %1};" : "=l"(r) : "r"(__float_as_uint(v)));
    return r;
}
__device__ __forceinline__ void ffma2(unsigned long long& acc,
                                      unsigned long long a,
                                      unsigned long long b){
    asm("fma.rn.f32x2 %0, %1, %2, %0;" : "+l"(acc) : "l"(a), "l"(b));
}
__device__ __forceinline__ float2 unpk2(unsigned long long v){
    unsigned int lo, hi;
    asm("mov.b64 {%0, %1}, %2;" : "=r"(lo), "=r"(hi) : "l"(v));
    return make_float2(__uint_as_float(lo), __uint_as_float(hi));
}

// smem floats:
//  x0,x1,aggx,aggy                  80
//  hS,hA,hB,mag   4*20*68         5440
//  buf  (A1 | Mm alias) 64*68     4352
//  w1c,b1v,b2v,avv,cb1v,c2v        384
//  cdx,cdy        2*64             128
//  r/c int16 tables                384
#define SMEM_FLOATS (80 + 4*NNODE*SH + ETILE*SMM + 6*64 + 2*ETILE + 384)

__global__ void __launch_bounds__(BLK, 4)
egnn_critic_kernel(
    const float* __restrict__ obs,   const float* __restrict__ rnn,
    const float* __restrict__ emb_w, const float* __restrict__ emb_b,
    const float* __restrict__ ew1,   const float* __restrict__ eb1,
    const float* __restrict__ ew2,   const float* __restrict__ eb2,
    const float* __restrict__ attw,  const float* __restrict__ attb,
    const float* __restrict__ nw1,   const float* __restrict__ nb1,
    const float* __restrict__ nw2,   const float* __restrict__ nb2,
    const float* __restrict__ cw1,   const float* __restrict__ cb1,
    const float* __restrict__ cw2,
    const float* __restrict__ fc1w,  const float* __restrict__ fc1b,
    const float* __restrict__ fc2w,  const float* __restrict__ fc2b,
    float* __restrict__ out, int copy_rnn)
{
    extern __shared__ float sm[];
    float* x0   = sm;
    float* x1   = x0 + NNODE;
    float* aggx = x1 + NNODE;
    float* aggy = aggx + NNODE;
    float* hS   = aggy + NNODE;          // [20][SH]
    float* hA   = hS + NNODE*SH;
    float* hB   = hA + NNODE*SH;
    float* mag  = hB + NNODE*SH;
    float* buf  = mag + NNODE*SH;        // A1 / Mm edge-major [64][SMM]
    float* w1c  = buf + ETILE*SMM;
    float* b1v  = w1c + 64;
    float* b2v  = b1v + 64;
    float* avv  = b2v + 64;
    float* cb1v = avv + 64;
    float* c2v  = cb1v + 64;
    float* cdx  = c2v + 64;
    float* cdy  = cdx + ETILE;
    short* rS   = (short*)(cdy + ETILE);      // [380]
    short* cS   = rS + 384;                   // [380]

    const int g = blockIdx.x;
    const int t = threadIdx.x;
    const float* ob = obs + g * NNODE * 10;   // EQU+INV = 10 per node

    // ---- edge index tables (per block, once) ----
    for (int e = t; e < NEDGE; e += BLK){
        int r = e / 19, jj = e - 19*r;
        rS[e] = (short)r;
        cS[e] = (short)(jj + (jj >= r));
    }
    // ---- init x, h ----
    if (t < NNODE){ x0[t] = ob[t*10 + 0]; x1[t] = ob[t*10 + 1]; }
    {
        int d = t & 63, ng = t >> 6;
        #pragma unroll
        for (int q = 0; q < 5; ++q){
            int n = ng + 4*q;
            float acc = emb_b[d];
            #pragma unroll
            for (int k = 0; k < 8; ++k) acc += ob[n*10 + 2 + k] * __ldg(emb_w + k*64 + d);
            hS[n*SH + d] = acc;
        }
    }
    __syncthreads();

    for (int l = 0; l < NL; ++l){
        // ---- stage per-layer vectors, zero accumulators ----
        if (t < 64){
            w1c[t]  = ew1[l*129*64 + 128*64 + t];
            b1v[t]  = eb1[l*64 + t];
            b2v[t]  = eb2[l*64 + t];
            avv[t]  = attw[l*64 + t];
            cb1v[t] = cb1[l*64 + t];
            c2v[t]  = cw2[l*64 + t];
        }
        if (t < NNODE){ aggx[t] = 0.f; aggy[t] = 0.f; }
        for (int i = t; i < NNODE*SH; i += BLK) mag[i] = 0.f;
        __syncthreads();

        const float ab = __ldg(attb + l);

        // ---- hA = h @ W1[0:64] + b1 (bias folded), hB = h @ W1[64:128] ----
        {
            int o = t & 63, ng = t >> 6;
            float aA[5], aB[5];
            #pragma unroll
            for (int q = 0; q < 5; ++q){ aA[q] = 0.f; aB[q] = 0.f; }
            const float* w1l = ew1 + l*129*64;
            #pragma unroll 4
            for (int k4 = 0; k4 < 64; k4 += 4){
                float wa[4], wb[4];
                #pragma unroll
                for (int kk = 0; kk < 4; ++kk){
                    wa[kk] = __ldg(w1l + (k4+kk)*64 + o);
                    wb[kk] = __ldg(w1l + (64 + k4+kk)*64 + o);
                }
                #pragma unroll
                for (int q = 0; q < 5; ++q){
                    float4 hv = *(const float4*)(hS + (ng + 4*q)*SH + k4);
                    aA[q] = fmaf(hv.x, wa[0], aA[q]); aB[q] = fmaf(hv.x, wb[0], aB[q]);
                    aA[q] = fmaf(hv.y, wa[1], aA[q]); aB[q] = fmaf(hv.y, wb[1], aB[q]);
                    aA[q] = fmaf(hv.z, wa[2], aA[q]); aB[q] = fmaf(hv.z, wb[2], aB[q]);
                    aA[q] = fmaf(hv.w, wa[3], aA[q]); aB[q] = fmaf(hv.w, wb[3], aB[q]);
                }
            }
            float bfold = b1v[o];
            #pragma unroll
            for (int q = 0; q < 5; ++q){
                hA[(ng + 4*q)*SH + o] = aA[q] + bfold;   // b1 folded into hA
                hB[(ng + 4*q)*SH + o] = aB[q];
            }
        }
        __syncthreads();

        const ulonglong2* W2g = reinterpret_cast<const ulonglong2*>(ew2 + l*4096);
        const ulonglong2* C1g = reinterpret_cast<const ulonglong2*>(cw1 + l*4096);

        // ---- edge tiles (64 edges) ----
        for (int tile = 0; tile < NTILE; ++tile){
            const int e0 = tile * ETILE;

            // A1 = silu(hA[r] + hB[c] + radial*w1c)  (b1 already in hA)
            {
                int le = t & 63, kg = t >> 6;   // kg: 16 ks each
                int e = e0 + le;
                bool v = (e < NEDGE);
                int r = 0, c = 0; float radial = 0.f;
                if (v){
                    r = rS[e]; c = cS[e];
                    float dx = x0[r] - x0[c], dy = x1[r] - x1[c];
                    radial = dx*dx + dy*dy;
                    if (kg == 0){
                        float inv = 1.f / (sqrtf(radial) + 1e-8f);
                        cdx[le] = dx * inv; cdy[le] = dy * inv;
                    }
                }
                int kbeg = kg * 16;
                #pragma unroll 4
                for (int k4 = kbeg; k4 < kbeg + 16; k4 += 4){
                    float4 o4 = make_float4(0.f, 0.f, 0.f, 0.f);
                    if (v){
                        float4 ha = *(const float4*)(hA + r*SH + k4);
                        float4 hb = *(const float4*)(hB + c*SH + k4);
                        float4 wc = *(const float4*)(w1c + k4);
                        o4.x = silu_f(fmaf(radial, wc.x, ha.x + hb.x));
                        o4.y = silu_f(fmaf(radial, wc.y, ha.y + hb.y));
                        o4.z = silu_f(fmaf(radial, wc.z, ha.z + hb.z));
                        o4.w = silu_f(fmaf(radial, wc.w, ha.w + hb.w));
                    }
                    *(float4*)(buf + le*SMM + k4) = o4;
                }
            }
            __syncthreads();

            // GEMM1 (FFMA2): m = silu(A1 @ W2 + b2) gated by sigmoid(att)
            // epilogue fuses the m_agg segment sum (atomics from registers)
            {
                int tx = t & 15, ty = t >> 4;     // outs 4tx.., edges 4ty..
                unsigned long long acc[4][2];     // [edge][out-pair]
                #pragma unroll
                for (int i = 0; i < 4; ++i){ acc[i][0] = 0ull; acc[i][1] = 0ull; }
                const ulonglong2* Bp = W2g + tx;
                #pragma unroll 4
                for (int k4 = 0; k4 < 64; k4 += 4){
                    float4 a0 = *(const float4*)(buf + (4*ty+0)*SMM + k4);
                    float4 a1 = *(const float4*)(buf + (4*ty+1)*SMM + k4);
                    float4 a2 = *(const float4*)(buf + (4*ty+2)*SMM + k4);
                    float4 a3 = *(const float4*)(buf + (4*ty+3)*SMM + k4);
                    #pragma unroll
                    for (int kk = 0; kk < 4; ++kk){
                        ulonglong2 b = __ldg(Bp + (k4 + kk)*16);
                        unsigned long long d0 = dup2(((float*)&a0)[kk]);
                        unsigned long long d1 = dup2(((float*)&a1)[kk]);
                        unsigned long long d2 = dup2(((float*)&a2)[kk]);
                        unsigned long long d3 = dup2(((float*)&a3)[kk]);
                        ffma2(acc[0][0], d0, b.x); ffma2(acc[0][1], d0, b.y);
                        ffma2(acc[1][0], d1, b.x); ffma2(acc[1][1], d1, b.y);
                        ffma2(acc[2][0], d2, b.x); ffma2(acc[2][1], d2, b.y);
                        ffma2(acc[3][0], d3, b.x); ffma2(acc[3][1], d3, b.y);
                    }
                }
                float mz[4][4];
                float attp[4];
                #pragma unroll
                for (int i = 0; i < 4; ++i){
                    float2 p0 = unpk2(acc[i][0]);
                    float2 p1 = unpk2(acc[i][1]);
                    float z0 = silu_f(p0.x + b2v[4*tx + 0]);
                    float z1 = silu_f(p0.y + b2v[4*tx + 1]);
                    float z2 = silu_f(p1.x + b2v[4*tx + 2]);
                    float z3 = silu_f(p1.y + b2v[4*tx + 3]);
                    mz[i][0] = z0; mz[i][1] = z1; mz[i][2] = z2; mz[i][3] = z3;
                    attp[i] = z0*avv[4*tx+0] + z1*avv[4*tx+1]
                            + z2*avv[4*tx+2] + z3*avv[4*tx+3];
                }
                #pragma unroll
                for (int m = 8; m >= 1; m >>= 1){
                    #pragma unroll
                    for (int i = 0; i < 4; ++i)
                        attp[i] += __shfl_xor_sync(0xffffffffu, attp[i], m, 16);
                }
                float sg[4];
                #pragma unroll
                for (int i = 0; i < 4; ++i) sg[i] = sigm_f(attp[i] + ab);

                __syncthreads();   // all A1 reads done -> overwrite buf as Mm

                // gate, store Mm, and accumulate segment sums from registers
                float s0 = 0.f, s1 = 0.f, s2 = 0.f, s3 = 0.f;
                int curr = -1;
                #pragma unroll
                for (int i = 0; i < 4; ++i){
                    float4 mv = make_float4(mz[i][0]*sg[i], mz[i][1]*sg[i],
                                            mz[i][2]*sg[i], mz[i][3]*sg[i]);
                    *(float4*)(buf + (4*ty + i)*SMM + 4*tx) = mv;
                    int e = e0 + 4*ty + i;
                    if (e < NEDGE){
                        int r = rS[e];
                        if (r != curr){
                            if (curr >= 0){
                                atomicAdd(mag + curr*SH + 4*tx + 0, s0);
                                atomicAdd(mag + curr*SH + 4*tx + 1, s1);
                                atomicAdd(mag + curr*SH + 4*tx + 2, s2);
                                atomicAdd(mag + curr*SH + 4*tx + 3, s3);
                            }
                            curr = r; s0 = s1 = s2 = s3 = 0.f;
                        }
                        s0 += mv.x; s1 += mv.y; s2 += mv.z; s3 += mv.w;
                    }
                }
                if (curr >= 0){
                    atomicAdd(mag + curr*SH + 4*tx + 0, s0);
                    atomicAdd(mag + curr*SH + 4*tx + 1, s1);
                    atomicAdd(mag + curr*SH + 4*tx + 2, s2);
                    atomicAdd(mag + curr*SH + 4*tx + 3, s3);
                }
            }
            __syncthreads();

            // GEMM2 (FFMA2): t3 = silu(Mm @ cw1 + cb1); w = tanh(t3 @ cw2); scatter
            {
                int tx = t & 15, ty = t >> 4;
                unsigned long long acc[4][2];
                #pragma unroll
                for (int i = 0; i < 4; ++i){ acc[i][0] = 0ull; acc[i][1] = 0ull; }
                const ulonglong2* Bp = C1g + tx;
                #pragma unroll 4
                for (int k4 = 0; k4 < 64; k4 += 4){
                    float4 a0 = *(const float4*)(buf + (4*ty+0)*SMM + k4);
                    float4 a1 = *(const float4*)(buf + (4*ty+1)*SMM + k4);
                    float4 a2 = *(const float4*)(buf + (4*ty+2)*SMM + k4);
                    float4 a3 = *(const float4*)(buf + (4*ty+3)*SMM + k4);
                    #pragma unroll
                    for (int kk = 0; kk < 4; ++kk){
                        ulonglong2 b = __ldg(Bp + (k4 + kk)*16);
                        unsigned long long d0 = dup2(((float*)&a0)[kk]);
                        unsigned long long d1 = dup2(((float*)&a1)[kk]);
                        unsigned long long d2 = dup2(((float*)&a2)[kk]);
                        unsigned long long d3 = dup2(((float*)&a3)[kk]);
                        ffma2(acc[0][0], d0, b.x); ffma2(acc[0][1], d0, b.y);
                        ffma2(acc[1][0], d1, b.x); ffma2(acc[1][1], d1, b.y);
                        ffma2(acc[2][0], d2, b.x); ffma2(acc[2][1], d2, b.y);
                        ffma2(acc[3][0], d3, b.x); ffma2(acc[3][1], d3, b.y);
                    }
                }
                float wp[4];
                #pragma unroll
                for (int i = 0; i < 4; ++i){
                    float2 p0 = unpk2(acc[i][0]);
                    float2 p1 = unpk2(acc[i][1]);
                    float z0 = silu_f(p0.x + cb1v[4*tx + 0]);
                    float z1 = silu_f(p0.y + cb1v[4*tx + 1]);
                    float z2 = silu_f(p1.x + cb1v[4*tx + 2]);
                    float z3 = silu_f(p1.y + cb1v[4*tx + 3]);
                    wp[i] = z0*c2v[4*tx+0] + z1*c2v[4*tx+1]
                          + z2*c2v[4*tx+2] + z3*c2v[4*tx+3];
                }
                #pragma unroll
                for (int m = 8; m >= 1; m >>= 1){
                    #pragma unroll
                    for (int i = 0; i < 4; ++i)
                        wp[i] += __shfl_xor_sync(0xffffffffu, wp[i], m, 16);
                }
                if (tx == 0){
                    #pragma unroll
                    for (int i = 0; i < 4; ++i){
                        int le = 4*ty + i, e = e0 + le;
                        if (e < NEDGE){
                            float w = tanh_a(wp[i]);
                            int r = rS[e];
                            atomicAdd(aggx + r, cdx[le] * w);
                            atomicAdd(aggy + r, cdy[le] * w);
                        }
                    }
                }
            }
            __syncthreads();   // protects buf/cdx/cdy before next tile
        } // tiles

        // ---- x update (cnt == 19 exactly) ----
        if (t < NNODE){
            x0[t] += aggx[t] * (1.f/19.f);
            x1[t] += aggy[t] * (1.f/19.f);
        }

        // ---- node MLP: h += silu([h,m_agg]@nw1+nb1) @ nw2 + nb2  (k vectorized x4) ----
        float* z1 = buf;  // rows stride SH
        {
            int o = t & 63, ng = t >> 6;
            float acc[5];
            float bb = __ldg(nb1 + l*64 + o);
            #pragma unroll
            for (int q = 0; q < 5; ++q) acc[q] = bb;
            const float* w1 = nw1 + l*128*64;
            #pragma unroll 4
            for (int k4 = 0; k4 < 64; k4 += 4){
                float w[4];
                #pragma unroll
                for (int kk = 0; kk < 4; ++kk) w[kk] = __ldg(w1 + (k4+kk)*64 + o);
                #pragma unroll
                for (int q = 0; q < 5; ++q){
                    float4 hv = *(const float4*)(hS + (ng + 4*q)*SH + k4);
                    acc[q] = fmaf(hv.x, w[0], acc[q]);
                    acc[q] = fmaf(hv.y, w[1], acc[q]);
                    acc[q] = fmaf(hv.z, w[2], acc[q]);
                    acc[q] = fmaf(hv.w, w[3], acc[q]);
                }
            }
            #pragma unroll 4
            for (int k4 = 0; k4 < 64; k4 += 4){
                float w[4];
                #pragma unroll
                for (int kk = 0; kk < 4; ++kk) w[kk] = __ldg(w1 + (64 + k4+kk)*64 + o);
                #pragma unroll
                for (int q = 0; q < 5; ++q){
                    float4 hv = *(const float4*)(mag + (ng + 4*q)*SH + k4);
                    acc[q] = fmaf(hv.x, w[0], acc[q]);
                    acc[q] = fmaf(hv.y, w[1], acc[q]);
                    acc[q] = fmaf(hv.z, w[2], acc[q]);
                    acc[q] = fmaf(hv.w, w[3], acc[q]);
                }
            }
            #pragma unroll
            for (int q = 0; q < 5; ++q) z1[(ng + 4*q)*SH + o] = silu_f(acc[q]);
        }
        __syncthreads();
        {
            int o = t & 63, ng = t >> 6;
            float acc[5];
            float bb = __ldg(nb2 + l*64 + o);
            #pragma unroll
            for (int q = 0; q < 5; ++q) acc[q] = bb;
            const float* w2 = nw2 + l*4096;
            #pragma unroll 4
            for (int k4 = 0; k4 < 64; k4 += 4){
                float w[4];
                #pragma unroll
                for (int kk = 0; kk < 4; ++kk) w[kk] = __ldg(w2 + (k4+kk)*64 + o);
                #pragma unroll
                for (int q = 0; q < 5; ++q){
                    float4 zv = *(const float4*)(z1 + (ng + 4*q)*SH + k4);
                    acc[q] = fmaf(zv.x, w[0], acc[q]);
                    acc[q] = fmaf(zv.y, w[1], acc[q]);
                    acc[q] = fmaf(zv.z, w[2], acc[q]);
                    acc[q] = fmaf(zv.w, w[3], acc[q]);
                }
            }
            #pragma unroll
            for (int q = 0; q < 5; ++q) hS[(ng + 4*q)*SH + o] += acc[q];
        }
        __syncthreads();
    } // layers

    // ---- value head ----
    float* z1 = buf;
    {
        int o = t & 63, ng = t >> 6;
        float acc[5];
        #pragma unroll
        for (int q = 0; q < 5; ++q){
            int n = ng + 4*q;
            float xsq = x0[n]*x0[n] + x1[n]*x1[n];
            acc[q] = fmaf(xsq, __ldg(fc1w + o), fc1b[o]);
        }
        #pragma unroll 4
        for (int k4 = 0; k4 < 64; k4 += 4){
            float w[4];
            #pragma unroll
            for (int kk = 0; kk < 4; ++kk) w[kk] = __ldg(fc1w + (1 + k4+kk)*64 + o);
            #pragma unroll
            for (int q = 0; q < 5; ++q){
                float4 hv = *(const float4*)(hS + (ng + 4*q)*SH + k4);
                acc[q] = fmaf(hv.x, w[0], acc[q]);
                acc[q] = fmaf(hv.y, w[1], acc[q]);
                acc[q] = fmaf(hv.z, w[2], acc[q]);
                acc[q] = fmaf(hv.w, w[3], acc[q]);
            }
        }
        #pragma unroll
        for (int q = 0; q < 5; ++q) z1[(ng + 4*q)*SH + o] = tanh_a(acc[q]);
    }
    __syncthreads();
    if (t < 32){
        float v = 0.f;
        if (t < NNODE){
            v = __ldg(fc2b);
            #pragma unroll 4
            for (int k4 = 0; k4 < 64; k4 += 4){
                float4 z = *(const float4*)(z1 + t*SH + k4);
                float4 w = *(const float4*)(fc2w + k4);
                v = fmaf(z.x, w.x, v); v = fmaf(z.y, w.y, v);
                v = fmaf(z.z, w.z, v); v = fmaf(z.w, w.w, v);
            }
        }
        #pragma unroll
        for (int m = 16; m >= 1; m >>= 1) v += __shfl_xor_sync(0xffffffffu, v, m);
        if (t == 0) out[g] = v * (1.f / NNODE);
    }
    // rnn_states passthrough
    if (copy_rnn && t < 64) out[NB + g*64 + t] = rnn[g*64 + t];
}

extern "C" void kernel_launch(void* const* d_in, const int* in_sizes, int n_in,
                              void* d_out, int out_size)
{
    const float* obs   = (const float*)d_in[0];
    const float* rnn   = (const float*)d_in[1];
    // d_in[2] = masks (unused)
    const float* emb_w = (const float*)d_in[3];
    const float* emb_b = (const float*)d_in[4];
    const float* ew1   = (const float*)d_in[5];
    const float* eb1   = (const float*)d_in[6];
    const float* ew2   = (const float*)d_in[7];
    const float* eb2   = (const float*)d_in[8];
    const float* attw  = (const float*)d_in[9];
    const float* attb  = (const float*)d_in[10];
    const float* nw1   = (const float*)d_in[11];
    const float* nb1   = (const float*)d_in[12];
    const float* nw2   = (const float*)d_in[13];
    const float* nb2   = (const float*)d_in[14];
    const float* cw1   = (const float*)d_in[15];
    const float* cb1   = (const float*)d_in[16];
    const float* cw2   = (const float*)d_in[17];
    const float* fc1w  = (const float*)d_in[18];
    const float* fc1b  = (const float*)d_in[19];
    const float* fc2w  = (const float*)d_in[20];
    const float* fc2b  = (const float*)d_in[21];
    // d_in[22], d_in[23] = edge_row/edge_col (recomputed analytically)

    const size_t smem_bytes = (size_t)SMEM_FLOATS * sizeof(float);
    cudaFuncSetAttribute(egnn_critic_kernel,
                         cudaFuncAttributeMaxDynamicSharedMemorySize,
                         (int)smem_bytes);

    int copy_rnn = (out_size >= NB + NB*HID) ? 1 : 0;

    egnn_critic_kernel<<<NB, BLK, smem_bytes>>>(
        obs, rnn, emb_w, emb_b, ew1, eb1, ew2, eb2, attw, attb,
        nw1, nb1, nw2, nb2, cw1, cb1, cw2, fc1w, fc1b, fc2w, fc2b,
        (float*)d_out, copy_rnn);
}

// round 10
// speedup vs baseline: 1.5762x; 1.5762x over previous
#include <cuda_runtime.h>
#include <math.h>

#define NNODE 20
#define NEDGE 380
#define HID   64
#define NL    3
#define ETILE 64
#define NTILE 6      // ceil(380/64)
#define SH    68     // stride for h-like [20][*] arrays (float4-aligned)
#define SMM   68     // buf edge-major stride (float4 aligned)
#define BLK   256
#define NB    1024

__device__ __forceinline__ float tanh_a(float v){
    float r; asm("tanh.approx.f32 %0, %1;" : "=f"(r) : "f"(v)); return r;
}
// silu via fast divide: 2 MUFU + mul/add — short-lived temps, no Newton chain
__device__ __forceinline__ float silu_f(float v){
    return __fdividef(v, 1.f + __expf(-v));
}
__device__ __forceinline__ float sigm_f(float v){
    return __fdividef(1.f, 1.f + __expf(-v));
}

// packed fp32x2 helpers (sm_103a FFMA2 path — PTX-only, ptxas never auto-fuses)
__device__ __forceinline__ unsigned long long dup2(float v){
    unsigned long long r;
    asm("mov.b64 %0, {%1, %1};" : "=l"(r) : "r"(__float_as_uint(v)));
    return r;
}
__device__ __forceinline__ void ffma2(unsigned long long& acc,
                                      unsigned long long a,
                                      unsigned long long b){
    asm("fma.rn.f32x2 %0, %1, %2, %0;" : "+l"(acc) : "l"(a), "l"(b));
}
__device__ __forceinline__ float2 unpk2(unsigned long long v){
    unsigned int lo, hi;
    asm("mov.b64 {%0, %1}, %2;" : "=r"(lo), "=r"(hi) : "l"(v));
    return make_float2(__uint_as_float(lo), __uint_as_float(hi));
}

// smem floats:
//  x0,x1,aggx,aggy                  80
//  hS,hA,hB,mag   4*20*68         5440
//  buf  (A1 | Mm alias) 64*68     4352
//  w1c,b1v,b2v,avv,cb1v,c2v        384
//  cdx,cdy        2*64             128
//  r/c int16 tables                384
#define SMEM_FLOATS (80 + 4*NNODE*SH + ETILE*SMM + 6*64 + 2*ETILE + 384)

__global__ void __launch_bounds__(BLK, 4)
egnn_critic_kernel(
    const float* __restrict__ obs,   const float* __restrict__ rnn,
    const float* __restrict__ emb_w, const float* __restrict__ emb_b,
    const float* __restrict__ ew1,   const float* __restrict__ eb1,
    const float* __restrict__ ew2,   const float* __restrict__ eb2,
    const float* __restrict__ attw,  const float* __restrict__ attb,
    const float* __restrict__ nw1,   const float* __restrict__ nb1,
    const float* __restrict__ nw2,   const float* __restrict__ nb2,
    const float* __restrict__ cw1,   const float* __restrict__ cb1,
    const float* __restrict__ cw2,
    const float* __restrict__ fc1w,  const float* __restrict__ fc1b,
    const float* __restrict__ fc2w,  const float* __restrict__ fc2b,
    float* __restrict__ out, int copy_rnn)
{
    extern __shared__ float sm[];
    float* x0   = sm;
    float* x1   = x0 + NNODE;
    float* aggx = x1 + NNODE;
    float* aggy = aggx + NNODE;
    float* hS   = aggy + NNODE;          // [20][SH]
    float* hA   = hS + NNODE*SH;
    float* hB   = hA + NNODE*SH;
    float* mag  = hB + NNODE*SH;
    float* buf  = mag + NNODE*SH;        // A1 / Mm edge-major [64][SMM]
    float* w1c  = buf + ETILE*SMM;
    float* b1v  = w1c + 64;
    float* b2v  = b1v + 64;
    float* avv  = b2v + 64;
    float* cb1v = avv + 64;
    float* c2v  = cb1v + 64;
    float* cdx  = c2v + 64;
    float* cdy  = cdx + ETILE;
    short* rS   = (short*)(cdy + ETILE);      // [380]
    short* cS   = rS + 384;                   // [380]

    const int g = blockIdx.x;
    const int t = threadIdx.x;
    const float* ob = obs + g * NNODE * 10;   // EQU+INV = 10 per node

    // ---- edge index tables (per block, once) ----
    for (int e = t; e < NEDGE; e += BLK){
        int r = e / 19, jj = e - 19*r;
        rS[e] = (short)r;
        cS[e] = (short)(jj + (jj >= r));
    }
    // ---- init x, h ----
    if (t < NNODE){ x0[t] = ob[t*10 + 0]; x1[t] = ob[t*10 + 1]; }
    {
        int d = t & 63, ng = t >> 6;
        #pragma unroll
        for (int q = 0; q < 5; ++q){
            int n = ng + 4*q;
            float acc = emb_b[d];
            #pragma unroll
            for (int k = 0; k < 8; ++k) acc += ob[n*10 + 2 + k] * __ldg(emb_w + k*64 + d);
            hS[n*SH + d] = acc;
        }
    }
    __syncthreads();

    for (int l = 0; l < NL; ++l){
        // ---- stage per-layer vectors, zero accumulators ----
        if (t < 64){
            w1c[t]  = ew1[l*129*64 + 128*64 + t];
            b1v[t]  = eb1[l*64 + t];
            b2v[t]  = eb2[l*64 + t];
            avv[t]  = attw[l*64 + t];
            cb1v[t] = cb1[l*64 + t];
            c2v[t]  = cw2[l*64 + t];
        }
        if (t < NNODE){ aggx[t] = 0.f; aggy[t] = 0.f; }
        for (int i = t; i < NNODE*SH; i += BLK) mag[i] = 0.f;
        __syncthreads();

        const float ab = __ldg(attb + l);

        // ---- hA = h @ W1[0:64] + b1 (bias folded), hB = h @ W1[64:128] ----
        {
            int o = t & 63, ng = t >> 6;
            float aA[5], aB[5];
            #pragma unroll
            for (int q = 0; q < 5; ++q){ aA[q] = 0.f; aB[q] = 0.f; }
            const float* w1l = ew1 + l*129*64;
            #pragma unroll 4
            for (int k4 = 0; k4 < 64; k4 += 4){
                float wa[4], wb[4];
                #pragma unroll
                for (int kk = 0; kk < 4; ++kk){
                    wa[kk] = __ldg(w1l + (k4+kk)*64 + o);
                    wb[kk] = __ldg(w1l + (64 + k4+kk)*64 + o);
                }
                #pragma unroll
                for (int q = 0; q < 5; ++q){
                    float4 hv = *(const float4*)(hS + (ng + 4*q)*SH + k4);
                    aA[q] = fmaf(hv.x, wa[0], aA[q]); aB[q] = fmaf(hv.x, wb[0], aB[q]);
                    aA[q] = fmaf(hv.y, wa[1], aA[q]); aB[q] = fmaf(hv.y, wb[1], aB[q]);
                    aA[q] = fmaf(hv.z, wa[2], aA[q]); aB[q] = fmaf(hv.z, wb[2], aB[q]);
                    aA[q] = fmaf(hv.w, wa[3], aA[q]); aB[q] = fmaf(hv.w, wb[3], aB[q]);
                }
            }
            float bfold = b1v[o];
            #pragma unroll
            for (int q = 0; q < 5; ++q){
                hA[(ng + 4*q)*SH + o] = aA[q] + bfold;   // b1 folded into hA
                hB[(ng + 4*q)*SH + o] = aB[q];
            }
        }
        __syncthreads();

        const ulonglong2* W2g = reinterpret_cast<const ulonglong2*>(ew2 + l*4096);
        const ulonglong2* C1g = reinterpret_cast<const ulonglong2*>(cw1 + l*4096);

        // ---- edge tiles (64 edges) ----
        for (int tile = 0; tile < NTILE; ++tile){
            const int e0 = tile * ETILE;

            // A1 = silu(hA[r] + hB[c] + radial*w1c)  (b1 already in hA)
            {
                int le = t & 63, kg = t >> 6;   // kg: 16 ks each
                int e = e0 + le;
                bool v = (e < NEDGE);
                int r = 0, c = 0; float radial = 0.f;
                if (v){
                    r = rS[e]; c = cS[e];
                    float dx = x0[r] - x0[c], dy = x1[r] - x1[c];
                    radial = dx*dx + dy*dy;
                    if (kg == 0){
                        float inv = 1.f / (sqrtf(radial) + 1e-8f);
                        cdx[le] = dx * inv; cdy[le] = dy * inv;
                    }
                }
                int kbeg = kg * 16;
                #pragma unroll 4
                for (int k4 = kbeg; k4 < kbeg + 16; k4 += 4){
                    float4 o4 = make_float4(0.f, 0.f, 0.f, 0.f);
                    if (v){
                        float4 ha = *(const float4*)(hA + r*SH + k4);
                        float4 hb = *(const float4*)(hB + c*SH + k4);
                        float4 wc = *(const float4*)(w1c + k4);
                        o4.x = silu_f(fmaf(radial, wc.x, ha.x + hb.x));
                        o4.y = silu_f(fmaf(radial, wc.y, ha.y + hb.y));
                        o4.z = silu_f(fmaf(radial, wc.z, ha.z + hb.z));
                        o4.w = silu_f(fmaf(radial, wc.w, ha.w + hb.w));
                    }
                    *(float4*)(buf + le*SMM + k4) = o4;
                }
            }
            __syncthreads();

            // GEMM1 (FFMA2): m = silu(A1 @ W2 + b2) gated by sigmoid(att)
            // epilogue fuses the m_agg segment sum (atomics from registers)
            {
                int tx = t & 15, ty = t >> 4;     // outs 4tx.., edges 4ty..
                unsigned long long acc[4][2];     // [edge][out-pair]
                #pragma unroll
                for (int i = 0; i < 4; ++i){ acc[i][0] = 0ull; acc[i][1] = 0ull; }
                const ulonglong2* Bp = W2g + tx;
                #pragma unroll 4
                for (int k4 = 0; k4 < 64; k4 += 4){
                    float4 a0 = *(const float4*)(buf + (4*ty+0)*SMM + k4);
                    float4 a1 = *(const float4*)(buf + (4*ty+1)*SMM + k4);
                    float4 a2 = *(const float4*)(buf + (4*ty+2)*SMM + k4);
                    float4 a3 = *(const float4*)(buf + (4*ty+3)*SMM + k4);
                    #pragma unroll
                    for (int kk = 0; kk < 4; ++kk){
                        ulonglong2 b = __ldg(Bp + (k4 + kk)*16);
                        unsigned long long d0 = dup2(((float*)&a0)[kk]);
                        unsigned long long d1 = dup2(((float*)&a1)[kk]);
                        unsigned long long d2 = dup2(((float*)&a2)[kk]);
                        unsigned long long d3 = dup2(((float*)&a3)[kk]);
                        ffma2(acc[0][0], d0, b.x); ffma2(acc[0][1], d0, b.y);
                        ffma2(acc[1][0], d1, b.x); ffma2(acc[1][1], d1, b.y);
                        ffma2(acc[2][0], d2, b.x); ffma2(acc[2][1], d2, b.y);
                        ffma2(acc[3][0], d3, b.x); ffma2(acc[3][1], d3, b.y);
                    }
                }
                float mz[4][4];
                float attp[4];
                #pragma unroll
                for (int i = 0; i < 4; ++i){
                    float2 p0 = unpk2(acc[i][0]);
                    float2 p1 = unpk2(acc[i][1]);
                    float z0 = silu_f(p0.x + b2v[4*tx + 0]);
                    float z1 = silu_f(p0.y + b2v[4*tx + 1]);
                    float z2 = silu_f(p1.x + b2v[4*tx + 2]);
                    float z3 = silu_f(p1.y + b2v[4*tx + 3]);
                    mz[i][0] = z0; mz[i][1] = z1; mz[i][2] = z2; mz[i][3] = z3;
                    attp[i] = z0*avv[4*tx+0] + z1*avv[4*tx+1]
                            + z2*avv[4*tx+2] + z3*avv[4*tx+3];
                }
                #pragma unroll
                for (int m = 8; m >= 1; m >>= 1){
                    #pragma unroll
                    for (int i = 0; i < 4; ++i)
                        attp[i] += __shfl_xor_sync(0xffffffffu, attp[i], m, 16);
                }
                float sg[4];
                #pragma unroll
                for (int i = 0; i < 4; ++i) sg[i] = sigm_f(attp[i] + ab);

                __syncthreads();   // all A1 reads done -> overwrite buf as Mm

                // gate, store Mm, and accumulate segment sums from registers
                float s0 = 0.f, s1 = 0.f, s2 = 0.f, s3 = 0.f;
                int curr = -1;
                #pragma unroll
                for (int i = 0; i < 4; ++i){
                    float4 mv = make_float4(mz[i][0]*sg[i], mz[i][1]*sg[i],
                                            mz[i][2]*sg[i], mz[i][3]*sg[i]);
                    *(float4*)(buf + (4*ty + i)*SMM + 4*tx) = mv;
                    int e = e0 + 4*ty + i;
                    if (e < NEDGE){
                        int r = rS[e];
                        if (r != curr){
                            if (curr >= 0){
                                atomicAdd(mag + curr*SH + 4*tx + 0, s0);
                                atomicAdd(mag + curr*SH + 4*tx + 1, s1);
                                atomicAdd(mag + curr*SH + 4*tx + 2, s2);
                                atomicAdd(mag + curr*SH + 4*tx + 3, s3);
                            }
                            curr = r; s0 = s1 = s2 = s3 = 0.f;
                        }
                        s0 += mv.x; s1 += mv.y; s2 += mv.z; s3 += mv.w;
                    }
                }
                if (curr >= 0){
                    atomicAdd(mag + curr*SH + 4*tx + 0, s0);
                    atomicAdd(mag + curr*SH + 4*tx + 1, s1);
                    atomicAdd(mag + curr*SH + 4*tx + 2, s2);
                    atomicAdd(mag + curr*SH + 4*tx + 3, s3);
                }
            }
            __syncthreads();

            // GEMM2 (FFMA2): t3 = silu(Mm @ cw1 + cb1); w = tanh(t3 @ cw2); scatter
            {
                int tx = t & 15, ty = t >> 4;
                unsigned long long acc[4][2];
                #pragma unroll
                for (int i = 0; i < 4; ++i){ acc[i][0] = 0ull; acc[i][1] = 0ull; }
                const ulonglong2* Bp = C1g + tx;
                #pragma unroll 4
                for (int k4 = 0; k4 < 64; k4 += 4){
                    float4 a0 = *(const float4*)(buf + (4*ty+0)*SMM + k4);
                    float4 a1 = *(const float4*)(buf + (4*ty+1)*SMM + k4);
                    float4 a2 = *(const float4*)(buf + (4*ty+2)*SMM + k4);
                    float4 a3 = *(const float4*)(buf + (4*ty+3)*SMM + k4);
                    #pragma unroll
                    for (int kk = 0; kk < 4; ++kk){
                        ulonglong2 b = __ldg(Bp + (k4 + kk)*16);
                        unsigned long long d0 = dup2(((float*)&a0)[kk]);
                        unsigned long long d1 = dup2(((float*)&a1)[kk]);
                        unsigned long long d2 = dup2(((float*)&a2)[kk]);
                        unsigned long long d3 = dup2(((float*)&a3)[kk]);
                        ffma2(acc[0][0], d0, b.x); ffma2(acc[0][1], d0, b.y);
                        ffma2(acc[1][0], d1, b.x); ffma2(acc[1][1], d1, b.y);
                        ffma2(acc[2][0], d2, b.x); ffma2(acc[2][1], d2, b.y);
                        ffma2(acc[3][0], d3, b.x); ffma2(acc[3][1], d3, b.y);
                    }
                }
                float wp[4];
                #pragma unroll
                for (int i = 0; i < 4; ++i){
                    float2 p0 = unpk2(acc[i][0]);
                    float2 p1 = unpk2(acc[i][1]);
                    float z0 = silu_f(p0.x + cb1v[4*tx + 0]);
                    float z1 = silu_f(p0.y + cb1v[4*tx + 1]);
                    float z2 = silu_f(p1.x + cb1v[4*tx + 2]);
                    float z3 = silu_f(p1.y + cb1v[4*tx + 3]);
                    wp[i] = z0*c2v[4*tx+0] + z1*c2v[4*tx+1]
                          + z2*c2v[4*tx+2] + z3*c2v[4*tx+3];
                }
                #pragma unroll
                for (int m = 8; m >= 1; m >>= 1){
                    #pragma unroll
                    for (int i = 0; i < 4; ++i)
                        wp[i] += __shfl_xor_sync(0xffffffffu, wp[i], m, 16);
                }
                if (tx == 0){
                    #pragma unroll
                    for (int i = 0; i < 4; ++i){
                        int le = 4*ty + i, e = e0 + le;
                        if (e < NEDGE){
                            float w = tanh_a(wp[i]);
                            int r = rS[e];
                            atomicAdd(aggx + r, cdx[le] * w);
                            atomicAdd(aggy + r, cdy[le] * w);
                        }
                    }
                }
            }
            __syncthreads();   // protects buf/cdx/cdy before next tile
        } // tiles

        // ---- x update (cnt == 19 exactly) ----
        if (t < NNODE){
            x0[t] += aggx[t] * (1.f/19.f);
            x1[t] += aggy[t] * (1.f/19.f);
        }

        // ---- node MLP: h += silu([h,m_agg]@nw1+nb1) @ nw2 + nb2  (k vectorized x4) ----
        float* z1 = buf;  // rows stride SH
        {
            int o = t & 63, ng = t >> 6;
            float acc[5];
            float bb = __ldg(nb1 + l*64 + o);
            #pragma unroll
            for (int q = 0; q < 5; ++q) acc[q] = bb;
            const float* w1 = nw1 + l*128*64;
            #pragma unroll 4
            for (int k4 = 0; k4 < 64; k4 += 4){
                float w[4];
                #pragma unroll
                for (int kk = 0; kk < 4; ++kk) w[kk] = __ldg(w1 + (k4+kk)*64 + o);
                #pragma unroll
                for (int q = 0; q < 5; ++q){
                    float4 hv = *(const float4*)(hS + (ng + 4*q)*SH + k4);
                    acc[q] = fmaf(hv.x, w[0], acc[q]);
                    acc[q] = fmaf(hv.y, w[1], acc[q]);
                    acc[q] = fmaf(hv.z, w[2], acc[q]);
                    acc[q] = fmaf(hv.w, w[3], acc[q]);
                }
            }
            #pragma unroll 4
            for (int k4 = 0; k4 < 64; k4 += 4){
                float w[4];
                #pragma unroll
                for (int kk = 0; kk < 4; ++kk) w[kk] = __ldg(w1 + (64 + k4+kk)*64 + o);
                #pragma unroll
                for (int q = 0; q < 5; ++q){
                    float4 hv = *(const float4*)(mag + (ng + 4*q)*SH + k4);
                    acc[q] = fmaf(hv.x, w[0], acc[q]);
                    acc[q] = fmaf(hv.y, w[1], acc[q]);
                    acc[q] = fmaf(hv.z, w[2], acc[q]);
                    acc[q] = fmaf(hv.w, w[3], acc[q]);
                }
            }
            #pragma unroll
            for (int q = 0; q < 5; ++q) z1[(ng + 4*q)*SH + o] = silu_f(acc[q]);
        }
        __syncthreads();
        {
            int o = t & 63, ng = t >> 6;
            float acc[5];
            float bb = __ldg(nb2 + l*64 + o);
            #pragma unroll
            for (int q = 0; q < 5; ++q) acc[q] = bb;
            const float* w2 = nw2 + l*4096;
            #pragma unroll 4
            for (int k4 = 0; k4 < 64; k4 += 4){
                float w[4];
                #pragma unroll
                for (int kk = 0; kk < 4; ++kk) w[kk] = __ldg(w2 + (k4+kk)*64 + o);
                #pragma unroll
                for (int q = 0; q < 5; ++q){
                    float4 zv = *(const float4*)(z1 + (ng + 4*q)*SH + k4);
                    acc[q] = fmaf(zv.x, w[0], acc[q]);
                    acc[q] = fmaf(zv.y, w[1], acc[q]);
                    acc[q] = fmaf(zv.z, w[2], acc[q]);
                    acc[q] = fmaf(zv.w, w[3], acc[q]);
                }
            }
            #pragma unroll
            for (int q = 0; q < 5; ++q) hS[(ng + 4*q)*SH + o] += acc[q];
        }
        __syncthreads();
    } // layers

    // ---- value head ----
    float* z1 = buf;
    {
        int o = t & 63, ng = t >> 6;
        float acc[5];
        #pragma unroll
        for (int q = 0; q < 5; ++q){
            int n = ng + 4*q;
            float xsq = x0[n]*x0[n] + x1[n]*x1[n];
            acc[q] = fmaf(xsq, __ldg(fc1w + o), fc1b[o]);
        }
        #pragma unroll 4
        for (int k4 = 0; k4 < 64; k4 += 4){
            float w[4];
            #pragma unroll
            for (int kk = 0; kk < 4; ++kk) w[kk] = __ldg(fc1w + (1 + k4+kk)*64 + o);
            #pragma unroll
            for (int q = 0; q < 5; ++q){
                float4 hv = *(const float4*)(hS + (ng + 4*q)*SH + k4);
                acc[q] = fmaf(hv.x, w[0], acc[q]);
                acc[q] = fmaf(hv.y, w[1], acc[q]);
                acc[q] = fmaf(hv.z, w[2], acc[q]);
                acc[q] = fmaf(hv.w, w[3], acc[q]);
            }
        }
        #pragma unroll
        for (int q = 0; q < 5; ++q) z1[(ng + 4*q)*SH + o] = tanh_a(acc[q]);
    }
    __syncthreads();
    if (t < 32){
        float v = 0.f;
        if (t < NNODE){
            v = __ldg(fc2b);
            #pragma unroll 4
            for (int k4 = 0; k4 < 64; k4 += 4){
                float4 z = *(const float4*)(z1 + t*SH + k4);
                float4 w = *(const float4*)(fc2w + k4);
                v = fmaf(z.x, w.x, v); v = fmaf(z.y, w.y, v);
                v = fmaf(z.z, w.z, v); v = fmaf(z.w, w.w, v);
            }
        }
        #pragma unroll
        for (int m = 16; m >= 1; m >>= 1) v += __shfl_xor_sync(0xffffffffu, v, m);
        if (t == 0) out[g] = v * (1.f / NNODE);
    }
    // rnn_states passthrough
    if (copy_rnn && t < 64) out[NB + g*64 + t] = rnn[g*64 + t];
}

extern "C" void kernel_launch(void* const* d_in, const int* in_sizes, int n_in,
                              void* d_out, int out_size)
{
    const float* obs   = (const float*)d_in[0];
    const float* rnn   = (const float*)d_in[1];
    // d_in[2] = masks (unused)
    const float* emb_w = (const float*)d_in[3];
    const float* emb_b = (const float*)d_in[4];
    const float* ew1   = (const float*)d_in[5];
    const float* eb1   = (const float*)d_in[6];
    const float* ew2   = (const float*)d_in[7];
    const float* eb2   = (const float*)d_in[8];
    const float* attw  = (const float*)d_in[9];
    const float* attb  = (const float*)d_in[10];
    const float* nw1   = (const float*)d_in[11];
    const float* nb1   = (const float*)d_in[12];
    const float* nw2   = (const float*)d_in[13];
    const float* nb2   = (const float*)d_in[14];
    const float* cw1   = (const float*)d_in[15];
    const float* cb1   = (const float*)d_in[16];
    const float* cw2   = (const float*)d_in[17];
    const float* fc1w  = (const float*)d_in[18];
    const float* fc1b  = (const float*)d_in[19];
    const float* fc2w  = (const float*)d_in[20];
    const float* fc2b  = (const float*)d_in[21];
    // d_in[22], d_in[23] = edge_row/edge_col (recomputed analytically)

    const size_t smem_bytes = (size_t)SMEM_FLOATS * sizeof(float);
    cudaFuncSetAttribute(egnn_critic_kernel,
                         cudaFuncAttributeMaxDynamicSharedMemorySize,
                         (int)smem_bytes);

    int copy_rnn = (out_size >= NB + NB*HID) ? 1 : 0;

    egnn_critic_kernel<<<NB, BLK, smem_bytes>>>(
        obs, rnn, emb_w, emb_b, ew1, eb1, ew2, eb2, attw, attb,
        nw1, nb1, nw2, nb2, cw1, cb1, cw2, fc1w, fc1b, fc2w, fc2b,
        (float*)d_out, copy_rnn);
}

// round 11
// speedup vs baseline: 1.5764x; 1.0001x over previous
#include <cuda_runtime.h>
#include <math.h>

#define NNODE 20
#define NEDGE 380
#define HID   64
#define NL    3
#define ETILE 64
#define NTILE 6      // ceil(380/64)
#define SH    68     // stride for h-like [20][*] arrays (float4-aligned)
#define SMM   68     // buf edge-major stride (float4 aligned)
#define BLK   256
#define NB    1024

__device__ __forceinline__ float tanh_a(float v){
    float r; asm("tanh.approx.f32 %0, %1;" : "=f"(r) : "f"(v)); return r;
}
__device__ __forceinline__ float silu_f(float v){
    return __fdividef(v, 1.f + __expf(-v));
}
__device__ __forceinline__ float sigm_f(float v){
    return __fdividef(1.f, 1.f + __expf(-v));
}

// packed fp32x2 helpers (sm_103a FFMA2 path — PTX-only)
__device__ __forceinline__ unsigned long long dup2(float v){
    unsigned long long r;
    asm("mov.b64 %0, {%1, %1};" : "=l"(r) : "r"(__float_as_uint(v)));
    return r;
}
__device__ __forceinline__ void ffma2(unsigned long long& acc,
                                      unsigned long long a,
                                      unsigned long long b){
    asm("fma.rn.f32x2 %0, %1, %2, %0;" : "+l"(acc) : "l"(a), "l"(b));
}
__device__ __forceinline__ float2 unpk2(unsigned long long v){
    unsigned int lo, hi;
    asm("mov.b64 {%0, %1}, %2;" : "=r"(lo), "=r"(hi) : "l"(v));
    return make_float2(__uint_as_float(lo), __uint_as_float(hi));
}

#define SMEM_FLOATS (80 + 4*NNODE*SH + ETILE*SMM + 6*64 + 2*ETILE + 384)

__global__ void __launch_bounds__(BLK, 4)
egnn_critic_kernel(
    const float* __restrict__ obs,   const float* __restrict__ rnn,
    const float* __restrict__ emb_w, const float* __restrict__ emb_b,
    const float* __restrict__ ew1,   const float* __restrict__ eb1,
    const float* __restrict__ ew2,   const float* __restrict__ eb2,
    const float* __restrict__ attw,  const float* __restrict__ attb,
    const float* __restrict__ nw1,   const float* __restrict__ nb1,
    const float* __restrict__ nw2,   const float* __restrict__ nb2,
    const float* __restrict__ cw1,   const float* __restrict__ cb1,
    const float* __restrict__ cw2,
    const float* __restrict__ fc1w,  const float* __restrict__ fc1b,
    const float* __restrict__ fc2w,  const float* __restrict__ fc2b,
    float* __restrict__ out, int copy_rnn)
{
    extern __shared__ float sm[];
    float* x0   = sm;
    float* x1   = x0 + NNODE;
    float* aggx = x1 + NNODE;
    float* aggy = aggx + NNODE;
    float* hS   = aggy + NNODE;          // [20][SH]
    float* hA   = hS + NNODE*SH;
    float* hB   = hA + NNODE*SH;
    float* mag  = hB + NNODE*SH;
    float* buf  = mag + NNODE*SH;        // A1 / Mm edge-major [64][SMM]
    float* w1c  = buf + ETILE*SMM;
    float* b1v  = w1c + 64;
    float* b2v  = b1v + 64;
    float* avv  = b2v + 64;
    float* cb1v = avv + 64;
    float* c2v  = cb1v + 64;
    float* cdx  = c2v + 64;
    float* cdy  = cdx + ETILE;
    short* rS   = (short*)(cdy + ETILE);      // [380]
    short* cS   = rS + 384;                   // [380]

    const int g = blockIdx.x;
    const int t = threadIdx.x;
    const float* ob = obs + g * NNODE * 10;   // EQU+INV = 10 per node

    // ---- edge index tables (per block, once) ----
    for (int e = t; e < NEDGE; e += BLK){
        int r = e / 19, jj = e - 19*r;
        rS[e] = (short)r;
        cS[e] = (short)(jj + (jj >= r));
    }
    // ---- init x, h ----
    if (t < NNODE){ x0[t] = ob[t*10 + 0]; x1[t] = ob[t*10 + 1]; }
    {
        int d = t & 63, ng = t >> 6;
        #pragma unroll
        for (int q = 0; q < 5; ++q){
            int n = ng + 4*q;
            float acc = emb_b[d];
            #pragma unroll
            for (int k = 0; k < 8; ++k) acc += ob[n*10 + 2 + k] * __ldg(emb_w + k*64 + d);
            hS[n*SH + d] = acc;
        }
    }
    __syncthreads();

    for (int l = 0; l < NL; ++l){
        // ---- stage per-layer vectors, zero accumulators ----
        if (t < 64){
            w1c[t]  = ew1[l*129*64 + 128*64 + t];
            b1v[t]  = eb1[l*64 + t];
            b2v[t]  = eb2[l*64 + t];
            avv[t]  = attw[l*64 + t];
            cb1v[t] = cb1[l*64 + t];
            c2v[t]  = cw2[l*64 + t];
        }
        if (t < NNODE){ aggx[t] = 0.f; aggy[t] = 0.f; }
        for (int i = t; i < NNODE*SH; i += BLK) mag[i] = 0.f;
        __syncthreads();

        const float ab = __ldg(attb + l);

        // ---- hA = h @ W1[0:64] + b1 (folded), hB = h @ W1[64:128]
        //      FFMA2 GEMM: half = warps 0-3 (hA) / 4-7 (hB); active ty<5, 4 nodes x 4 outs
        {
            int half = t >> 7;
            int tx = t & 15;
            int ty = (t >> 4) & 7;
            if (ty < 5){
                int n0 = ty, n1 = ty + 5, n2 = ty + 10, n3 = ty + 15;
                unsigned long long acc[4][2];
                #pragma unroll
                for (int i = 0; i < 4; ++i){ acc[i][0] = 0ull; acc[i][1] = 0ull; }
                const ulonglong2* Wg =
                    reinterpret_cast<const ulonglong2*>(ew1 + l*129*64 + half*4096) + tx;
                #pragma unroll 4
                for (int k4 = 0; k4 < 64; k4 += 4){
                    float4 a0 = *(const float4*)(hS + n0*SH + k4);
                    float4 a1 = *(const float4*)(hS + n1*SH + k4);
                    float4 a2 = *(const float4*)(hS + n2*SH + k4);
                    float4 a3 = *(const float4*)(hS + n3*SH + k4);
                    #pragma unroll
                    for (int kk = 0; kk < 4; ++kk){
                        ulonglong2 b = __ldg(Wg + (k4 + kk)*16);
                        unsigned long long d0 = dup2(((float*)&a0)[kk]);
                        unsigned long long d1 = dup2(((float*)&a1)[kk]);
                        unsigned long long d2 = dup2(((float*)&a2)[kk]);
                        unsigned long long d3 = dup2(((float*)&a3)[kk]);
                        ffma2(acc[0][0], d0, b.x); ffma2(acc[0][1], d0, b.y);
                        ffma2(acc[1][0], d1, b.x); ffma2(acc[1][1], d1, b.y);
                        ffma2(acc[2][0], d2, b.x); ffma2(acc[2][1], d2, b.y);
                        ffma2(acc[3][0], d3, b.x); ffma2(acc[3][1], d3, b.y);
                    }
                }
                float* dst = half ? hB : hA;
                float4 bf = half ? make_float4(0.f,0.f,0.f,0.f)
                                 : *(const float4*)(b1v + 4*tx);
                int nn[4] = {n0, n1, n2, n3};
                #pragma unroll
                for (int i = 0; i < 4; ++i){
                    float2 p0 = unpk2(acc[i][0]);
                    float2 p1 = unpk2(acc[i][1]);
                    *(float4*)(dst + nn[i]*SH + 4*tx) =
                        make_float4(p0.x + bf.x, p0.y + bf.y, p1.x + bf.z, p1.y + bf.w);
                }
            }
        }
        __syncthreads();

        const ulonglong2* W2g = reinterpret_cast<const ulonglong2*>(ew2 + l*4096);
        const ulonglong2* C1g = reinterpret_cast<const ulonglong2*>(cw1 + l*4096);

        // ---- edge tiles (64 edges) ----
        for (int tile = 0; tile < NTILE; ++tile){
            const int e0 = tile * ETILE;

            // A1 = silu(hA[r] + hB[c] + radial*w1c)  (b1 already in hA)
            {
                int le = t & 63, kg = t >> 6;   // kg: 16 ks each
                int e = e0 + le;
                bool v = (e < NEDGE);
                int r = 0, c = 0; float radial = 0.f;
                if (v){
                    r = rS[e]; c = cS[e];
                    float dx = x0[r] - x0[c], dy = x1[r] - x1[c];
                    radial = dx*dx + dy*dy;
                    if (kg == 0){
                        float inv = 1.f / (sqrtf(radial) + 1e-8f);
                        cdx[le] = dx * inv; cdy[le] = dy * inv;
                    }
                }
                int kbeg = kg * 16;
                #pragma unroll 4
                for (int k4 = kbeg; k4 < kbeg + 16; k4 += 4){
                    float4 o4 = make_float4(0.f, 0.f, 0.f, 0.f);
                    if (v){
                        float4 ha = *(const float4*)(hA + r*SH + k4);
                        float4 hb = *(const float4*)(hB + c*SH + k4);
                        float4 wc = *(const float4*)(w1c + k4);
                        o4.x = silu_f(fmaf(radial, wc.x, ha.x + hb.x));
                        o4.y = silu_f(fmaf(radial, wc.y, ha.y + hb.y));
                        o4.z = silu_f(fmaf(radial, wc.z, ha.z + hb.z));
                        o4.w = silu_f(fmaf(radial, wc.w, ha.w + hb.w));
                    }
                    *(float4*)(buf + le*SMM + k4) = o4;
                }
            }
            __syncthreads();

            // GEMM1 (FFMA2): m = silu(A1 @ W2 + b2) gated by sigmoid(att)
            // epilogue fuses the m_agg segment sum (atomics from registers)
            {
                int tx = t & 15, ty = t >> 4;     // outs 4tx.., edges 4ty..
                unsigned long long acc[4][2];     // [edge][out-pair]
                #pragma unroll
                for (int i = 0; i < 4; ++i){ acc[i][0] = 0ull; acc[i][1] = 0ull; }
                const ulonglong2* Bp = W2g + tx;
                #pragma unroll 4
                for (int k4 = 0; k4 < 64; k4 += 4){
                    float4 a0 = *(const float4*)(buf + (4*ty+0)*SMM + k4);
                    float4 a1 = *(const float4*)(buf + (4*ty+1)*SMM + k4);
                    float4 a2 = *(const float4*)(buf + (4*ty+2)*SMM + k4);
                    float4 a3 = *(const float4*)(buf + (4*ty+3)*SMM + k4);
                    #pragma unroll
                    for (int kk = 0; kk < 4; ++kk){
                        ulonglong2 b = __ldg(Bp + (k4 + kk)*16);
                        unsigned long long d0 = dup2(((float*)&a0)[kk]);
                        unsigned long long d1 = dup2(((float*)&a1)[kk]);
                        unsigned long long d2 = dup2(((float*)&a2)[kk]);
                        unsigned long long d3 = dup2(((float*)&a3)[kk]);
                        ffma2(acc[0][0], d0, b.x); ffma2(acc[0][1], d0, b.y);
                        ffma2(acc[1][0], d1, b.x); ffma2(acc[1][1], d1, b.y);
                        ffma2(acc[2][0], d2, b.x); ffma2(acc[2][1], d2, b.y);
                        ffma2(acc[3][0], d3, b.x); ffma2(acc[3][1], d3, b.y);
                    }
                }
                float mz[4][4];
                float attp[4];
                #pragma unroll
                for (int i = 0; i < 4; ++i){
                    float2 p0 = unpk2(acc[i][0]);
                    float2 p1 = unpk2(acc[i][1]);
                    float z0 = silu_f(p0.x + b2v[4*tx + 0]);
                    float z1 = silu_f(p0.y + b2v[4*tx + 1]);
                    float z2 = silu_f(p1.x + b2v[4*tx + 2]);
                    float z3 = silu_f(p1.y + b2v[4*tx + 3]);
                    mz[i][0] = z0; mz[i][1] = z1; mz[i][2] = z2; mz[i][3] = z3;
                    attp[i] = z0*avv[4*tx+0] + z1*avv[4*tx+1]
                            + z2*avv[4*tx+2] + z3*avv[4*tx+3];
                }
                #pragma unroll
                for (int m = 8; m >= 1; m >>= 1){
                    #pragma unroll
                    for (int i = 0; i < 4; ++i)
                        attp[i] += __shfl_xor_sync(0xffffffffu, attp[i], m, 16);
                }
                float sg[4];
                #pragma unroll
                for (int i = 0; i < 4; ++i) sg[i] = sigm_f(attp[i] + ab);

                __syncthreads();   // all A1 reads done -> overwrite buf as Mm

                float s0 = 0.f, s1 = 0.f, s2 = 0.f, s3 = 0.f;
                int curr = -1;
                #pragma unroll
                for (int i = 0; i < 4; ++i){
                    float4 mv = make_float4(mz[i][0]*sg[i], mz[i][1]*sg[i],
                                            mz[i][2]*sg[i], mz[i][3]*sg[i]);
                    *(float4*)(buf + (4*ty + i)*SMM + 4*tx) = mv;
                    int e = e0 + 4*ty + i;
                    if (e < NEDGE){
                        int r = rS[e];
                        if (r != curr){
                            if (curr >= 0){
                                atomicAdd(mag + curr*SH + 4*tx + 0, s0);
                                atomicAdd(mag + curr*SH + 4*tx + 1, s1);
                                atomicAdd(mag + curr*SH + 4*tx + 2, s2);
                                atomicAdd(mag + curr*SH + 4*tx + 3, s3);
                            }
                            curr = r; s0 = s1 = s2 = s3 = 0.f;
                        }
                        s0 += mv.x; s1 += mv.y; s2 += mv.z; s3 += mv.w;
                    }
                }
                if (curr >= 0){
                    atomicAdd(mag + curr*SH + 4*tx + 0, s0);
                    atomicAdd(mag + curr*SH + 4*tx + 1, s1);
                    atomicAdd(mag + curr*SH + 4*tx + 2, s2);
                    atomicAdd(mag + curr*SH + 4*tx + 3, s3);
                }
            }
            __syncthreads();

            // GEMM2 (FFMA2): t3 = silu(Mm @ cw1 + cb1); w = tanh(t3 @ cw2); scatter
            {
                int tx = t & 15, ty = t >> 4;
                unsigned long long acc[4][2];
                #pragma unroll
                for (int i = 0; i < 4; ++i){ acc[i][0] = 0ull; acc[i][1] = 0ull; }
                const ulonglong2* Bp = C1g + tx;
                #pragma unroll 4
                for (int k4 = 0; k4 < 64; k4 += 4){
                    float4 a0 = *(const float4*)(buf + (4*ty+0)*SMM + k4);
                    float4 a1 = *(const float4*)(buf + (4*ty+1)*SMM + k4);
                    float4 a2 = *(const float4*)(buf + (4*ty+2)*SMM + k4);
                    float4 a3 = *(const float4*)(buf + (4*ty+3)*SMM + k4);
                    #pragma unroll
                    for (int kk = 0; kk < 4; ++kk){
                        ulonglong2 b = __ldg(Bp + (k4 + kk)*16);
                        unsigned long long d0 = dup2(((float*)&a0)[kk]);
                        unsigned long long d1 = dup2(((float*)&a1)[kk]);
                        unsigned long long d2 = dup2(((float*)&a2)[kk]);
                        unsigned long long d3 = dup2(((float*)&a3)[kk]);
                        ffma2(acc[0][0], d0, b.x); ffma2(acc[0][1], d0, b.y);
                        ffma2(acc[1][0], d1, b.x); ffma2(acc[1][1], d1, b.y);
                        ffma2(acc[2][0], d2, b.x); ffma2(acc[2][1], d2, b.y);
                        ffma2(acc[3][0], d3, b.x); ffma2(acc[3][1], d3, b.y);
                    }
                }
                float wp[4];
                #pragma unroll
                for (int i = 0; i < 4; ++i){
                    float2 p0 = unpk2(acc[i][0]);
                    float2 p1 = unpk2(acc[i][1]);
                    float z0 = silu_f(p0.x + cb1v[4*tx + 0]);
                    float z1 = silu_f(p0.y + cb1v[4*tx + 1]);
                    float z2 = silu_f(p1.x + cb1v[4*tx + 2]);
                    float z3 = silu_f(p1.y + cb1v[4*tx + 3]);
                    wp[i] = z0*c2v[4*tx+0] + z1*c2v[4*tx+1]
                          + z2*c2v[4*tx+2] + z3*c2v[4*tx+3];
                }
                #pragma unroll
                for (int m = 8; m >= 1; m >>= 1){
                    #pragma unroll
                    for (int i = 0; i < 4; ++i)
                        wp[i] += __shfl_xor_sync(0xffffffffu, wp[i], m, 16);
                }
                if (tx == 0){
                    #pragma unroll
                    for (int i = 0; i < 4; ++i){
                        int le = 4*ty + i, e = e0 + le;
                        if (e < NEDGE){
                            float w = tanh_a(wp[i]);
                            int r = rS[e];
                            atomicAdd(aggx + r, cdx[le] * w);
                            atomicAdd(aggy + r, cdy[le] * w);
                        }
                    }
                }
            }
            __syncthreads();   // protects buf/cdx/cdy before next tile
        } // tiles

        // ---- x update (cnt == 19 exactly) ----
        if (t < NNODE){
            x0[t] += aggx[t] * (1.f/19.f);
            x1[t] += aggy[t] * (1.f/19.f);
        }

        // ---- node MLP pass1 (FFMA2): z1 = silu([h,m_agg]@nw1 + nb1)
        //      active ty<10, 2 nodes x 4 outs
        float* z1 = buf;
        {
            int tx = t & 15, ty = t >> 4;
            if (ty < 10){
                int n0 = ty, n1 = ty + 10;
                unsigned long long acc[2][2];
                acc[0][0]=0ull; acc[0][1]=0ull; acc[1][0]=0ull; acc[1][1]=0ull;
                const ulonglong2* Wg =
                    reinterpret_cast<const ulonglong2*>(nw1 + l*8192) + tx;
                #pragma unroll 4
                for (int k4 = 0; k4 < 64; k4 += 4){
                    float4 a0 = *(const float4*)(hS + n0*SH + k4);
                    float4 a1 = *(const float4*)(hS + n1*SH + k4);
                    #pragma unroll
                    for (int kk = 0; kk < 4; ++kk){
                        ulonglong2 b = __ldg(Wg + (k4 + kk)*16);
                        unsigned long long d0 = dup2(((float*)&a0)[kk]);
                        unsigned long long d1 = dup2(((float*)&a1)[kk]);
                        ffma2(acc[0][0], d0, b.x); ffma2(acc[0][1], d0, b.y);
                        ffma2(acc[1][0], d1, b.x); ffma2(acc[1][1], d1, b.y);
                    }
                }
                #pragma unroll 4
                for (int k4 = 0; k4 < 64; k4 += 4){
                    float4 a0 = *(const float4*)(mag + n0*SH + k4);
                    float4 a1 = *(const float4*)(mag + n1*SH + k4);
                    #pragma unroll
                    for (int kk = 0; kk < 4; ++kk){
                        ulonglong2 b = __ldg(Wg + (64 + k4 + kk)*16);
                        unsigned long long d0 = dup2(((float*)&a0)[kk]);
                        unsigned long long d1 = dup2(((float*)&a1)[kk]);
                        ffma2(acc[0][0], d0, b.x); ffma2(acc[0][1], d0, b.y);
                        ffma2(acc[1][0], d1, b.x); ffma2(acc[1][1], d1, b.y);
                    }
                }
                float4 bb = __ldg(reinterpret_cast<const float4*>(nb1 + l*64) + tx);
                {
                    float2 p0 = unpk2(acc[0][0]), p1 = unpk2(acc[0][1]);
                    *(float4*)(z1 + n0*SH + 4*tx) = make_float4(
                        silu_f(p0.x + bb.x), silu_f(p0.y + bb.y),
                        silu_f(p1.x + bb.z), silu_f(p1.y + bb.w));
                }
                {
                    float2 p0 = unpk2(acc[1][0]), p1 = unpk2(acc[1][1]);
                    *(float4*)(z1 + n1*SH + 4*tx) = make_float4(
                        silu_f(p0.x + bb.x), silu_f(p0.y + bb.y),
                        silu_f(p1.x + bb.z), silu_f(p1.y + bb.w));
                }
            }
        }
        __syncthreads();

        // ---- node MLP pass2 (FFMA2): h += z1 @ nw2 + nb2 ----
        {
            int tx = t & 15, ty = t >> 4;
            if (ty < 10){
                int n0 = ty, n1 = ty + 10;
                unsigned long long acc[2][2];
                acc[0][0]=0ull; acc[0][1]=0ull; acc[1][0]=0ull; acc[1][1]=0ull;
                const ulonglong2* Wg =
                    reinterpret_cast<const ulonglong2*>(nw2 + l*4096) + tx;
                #pragma unroll 4
                for (int k4 = 0; k4 < 64; k4 += 4){
                    float4 a0 = *(const float4*)(z1 + n0*SH + k4);
                    float4 a1 = *(const float4*)(z1 + n1*SH + k4);
                    #pragma unroll
                    for (int kk = 0; kk < 4; ++kk){
                        ulonglong2 b = __ldg(Wg + (k4 + kk)*16);
                        unsigned long long d0 = dup2(((float*)&a0)[kk]);
                        unsigned long long d1 = dup2(((float*)&a1)[kk]);
                        ffma2(acc[0][0], d0, b.x); ffma2(acc[0][1], d0, b.y);
                        ffma2(acc[1][0], d1, b.x); ffma2(acc[1][1], d1, b.y);
                    }
                }
                float4 bb = __ldg(reinterpret_cast<const float4*>(nb2 + l*64) + tx);
                {
                    float2 p0 = unpk2(acc[0][0]), p1 = unpk2(acc[0][1]);
                    float4 h0 = *(const float4*)(hS + n0*SH + 4*tx);
                    h0.x += p0.x + bb.x; h0.y += p0.y + bb.y;
                    h0.z += p1.x + bb.z; h0.w += p1.y + bb.w;
                    *(float4*)(hS + n0*SH + 4*tx) = h0;
                }
                {
                    float2 p0 = unpk2(acc[1][0]), p1 = unpk2(acc[1][1]);
                    float4 h1 = *(const float4*)(hS + n1*SH + 4*tx);
                    h1.x += p0.x + bb.x; h1.y += p0.y + bb.y;
                    h1.z += p1.x + bb.z; h1.w += p1.y + bb.w;
                    *(float4*)(hS + n1*SH + 4*tx) = h1;
                }
            }
        }
        __syncthreads();
    } // layers

    // ---- value head (FFMA2): z1 = tanh([xsq,h] @ fc1w + fc1b) ----
    float* z1 = buf;
    {
        int tx = t & 15, ty = t >> 4;
        if (ty < 10){
            int n0 = ty, n1 = ty + 10;
            unsigned long long acc[2][2];
            acc[0][0]=0ull; acc[0][1]=0ull; acc[1][0]=0ull; acc[1][1]=0ull;
            const ulonglong2* Wg =
                reinterpret_cast<const ulonglong2*>(fc1w + 64) + tx;   // rows 1..64
            #pragma unroll 4
            for (int k4 = 0; k4 < 64; k4 += 4){
                float4 a0 = *(const float4*)(hS + n0*SH + k4);
                float4 a1 = *(const float4*)(hS + n1*SH + k4);
                #pragma unroll
                for (int kk = 0; kk < 4; ++kk){
                    ulonglong2 b = __ldg(Wg + (k4 + kk)*16);
                    unsigned long long d0 = dup2(((float*)&a0)[kk]);
                    unsigned long long d1 = dup2(((float*)&a1)[kk]);
                    ffma2(acc[0][0], d0, b.x); ffma2(acc[0][1], d0, b.y);
                    ffma2(acc[1][0], d1, b.x); ffma2(acc[1][1], d1, b.y);
                }
            }
            float4 w0 = __ldg(reinterpret_cast<const float4*>(fc1w) + tx);  // xsq row
            float4 bb = __ldg(reinterpret_cast<const float4*>(fc1b) + tx);
            float xsq0 = x0[n0]*x0[n0] + x1[n0]*x1[n0];
            float xsq1 = x0[n1]*x0[n1] + x1[n1]*x1[n1];
            {
                float2 p0 = unpk2(acc[0][0]), p1 = unpk2(acc[0][1]);
                *(float4*)(z1 + n0*SH + 4*tx) = make_float4(
                    tanh_a(fmaf(xsq0, w0.x, p0.x + bb.x)),
                    tanh_a(fmaf(xsq0, w0.y, p0.y + bb.y)),
                    tanh_a(fmaf(xsq0, w0.z, p1.x + bb.z)),
                    tanh_a(fmaf(xsq0, w0.w, p1.y + bb.w)));
            }
            {
                float2 p0 = unpk2(acc[1][0]), p1 = unpk2(acc[1][1]);
                *(float4*)(z1 + n1*SH + 4*tx) = make_float4(
                    tanh_a(fmaf(xsq1, w0.x, p0.x + bb.x)),
                    tanh_a(fmaf(xsq1, w0.y, p0.y + bb.y)),
                    tanh_a(fmaf(xsq1, w0.z, p1.x + bb.z)),
                    tanh_a(fmaf(xsq1, w0.w, p1.y + bb.w)));
            }
        }
    }
    __syncthreads();
    if (t < 32){
        float v = 0.f;
        if (t < NNODE){
            v = __ldg(fc2b);
            #pragma unroll 4
            for (int k4 = 0; k4 < 64; k4 += 4){
                float4 z = *(const float4*)(z1 + t*SH + k4);
                float4 w = *(const float4*)(fc2w + k4);
                v = fmaf(z.x, w.x, v); v = fmaf(z.y, w.y, v);
                v = fmaf(z.z, w.z, v); v = fmaf(z.w, w.w, v);
            }
        }
        #pragma unroll
        for (int m = 16; m >= 1; m >>= 1) v += __shfl_xor_sync(0xffffffffu, v, m);
        if (t == 0) out[g] = v * (1.f / NNODE);
    }
    // rnn_states passthrough
    if (copy_rnn && t < 64) out[NB + g*64 + t] = rnn[g*64 + t];
}

extern "C" void kernel_launch(void* const* d_in, const int* in_sizes, int n_in,
                              void* d_out, int out_size)
{
    const float* obs   = (const float*)d_in[0];
    const float* rnn   = (const float*)d_in[1];
    // d_in[2] = masks (unused)
    const float* emb_w = (const float*)d_in[3];
    const float* emb_b = (const float*)d_in[4];
    const float* ew1   = (const float*)d_in[5];
    const float* eb1   = (const float*)d_in[6];
    const float* ew2   = (const float*)d_in[7];
    const float* eb2   = (const float*)d_in[8];
    const float* attw  = (const float*)d_in[9];
    const float* attb  = (const float*)d_in[10];
    const float* nw1   = (const float*)d_in[11];
    const float* nb1   = (const float*)d_in[12];
    const float* nw2   = (const float*)d_in[13];
    const float* nb2   = (const float*)d_in[14];
    const float* cw1   = (const float*)d_in[15];
    const float* cb1   = (const float*)d_in[16];
    const float* cw2   = (const float*)d_in[17];
    const float* fc1w  = (const float*)d_in[18];
    const float* fc1b  = (const float*)d_in[19];
    const float* fc2w  = (const float*)d_in[20];
    const float* fc2b  = (const float*)d_in[21];
    // d_in[22], d_in[23] = edge_row/edge_col (recomputed analytically)

    const size_t smem_bytes = (size_t)SMEM_FLOATS * sizeof(float);
    cudaFuncSetAttribute(egnn_critic_kernel,
                         cudaFuncAttributeMaxDynamicSharedMemorySize,
                         (int)smem_bytes);

    int copy_rnn = (out_size >= NB + NB*HID) ? 1 : 0;

    egnn_critic_kernel<<<NB, BLK, smem_bytes>>>(
        obs, rnn, emb_w, emb_b, ew1, eb1, ew2, eb2, attw, attb,
        nw1, nb1, nw2, nb2, cw1, cb1, cw2, fc1w, fc1b, fc2w, fc2b,
        (float*)d_out, copy_rnn);
}